// round 3
// baseline (speedup 1.0000x reference)
#include <cuda_runtime.h>
#include <math.h>

#define NLAYERS 4
#define HID 64
#define NROWS 8192            // B*N = 2*4096
#define ROWS_PER_BLK 64
#define NBLK (NROWS / ROWS_PER_BLK)   // 128
#define DUP_S 132             // floats per j-row of duplicated (pair) arrays

typedef unsigned long long ull;

// Scratch (no allocations allowed): activations + per-layer k^T v accumulators.
__device__ float g_h[NROWS * HID];
__device__ float g_q[NROWS * HID];
__device__ float g_wh[NROWS * HID];
__device__ float g_M[NLAYERS * 2 * HID * HID];   // per layer, per batch, 64x64

// ---- packed fp32x2 helpers ----
__device__ __forceinline__ void ffma2(ull& d, ull a, ull b) {
    asm("fma.rn.f32x2 %0, %1, %2, %0;" : "+l"(d) : "l"(a), "l"(b));
}
__device__ __forceinline__ void add2(ull& d, ull a) {
    asm("add.rn.f32x2 %0, %0, %1;" : "+l"(d) : "l"(a));
}
__device__ __forceinline__ ull pack2(float x, float y) {
    ull r; asm("mov.b64 %0, {%1,%2};" : "=l"(r) : "f"(x), "f"(y)); return r;
}
__device__ __forceinline__ float2 unpack2(ull p) {
    float2 r; asm("mov.b64 {%0,%1}, %2;" : "=f"(r.x), "=f"(r.y) : "l"(p)); return r;
}

__device__ __forceinline__ float gelu_exact(float x) {
    return 0.5f * x * (1.0f + erff(x * 0.70710678118654752440f));
}

// ---------------------------------------------------------------------------
// lift: h = x @ lift_w + lift_b   ([8192,3] @ [3,64]); also zero all g_M.
// ---------------------------------------------------------------------------
__global__ __launch_bounds__(256) void lift_kernel(
    const float* __restrict__ x, const float* __restrict__ lw,
    const float* __restrict__ lb)
{
    int idx = blockIdx.x * 256 + threadIdx.x;      // 0 .. 524287
    int row = idx >> 6;
    int c   = idx & 63;
    const float* xr = x + row * 3;
    float acc = lb[c];
    acc = fmaf(xr[0], lw[c],        acc);
    acc = fmaf(xr[1], lw[64 + c],   acc);
    acc = fmaf(xr[2], lw[128 + c],  acc);
    g_h[idx] = acc;
    if (idx < NLAYERS * 2 * HID * HID) g_M[idx] = 0.0f;
}

// ---------------------------------------------------------------------------
// layerA (512 threads, 16 warps): [q|k|v|wh] = h @ [qw|kw|vw|bw] + bias for 64
// rows; write q,wh; reduce partial M = k^T v and atomicAdd.
// Thread map: ry = warp (4 rows), cy = lane (col pair 2cy in each matrix).
// ---------------------------------------------------------------------------
__global__ __launch_bounds__(512) void layerA_kernel(
    const float* __restrict__ qw, const float* __restrict__ qb,
    const float* __restrict__ kw, const float* __restrict__ kb,
    const float* __restrict__ vw, const float* __restrict__ vb,
    const float* __restrict__ bw, const float* __restrict__ bb,
    int layer)
{
    extern __shared__ float sm[];
    float* hd = sm;                    // 64*DUP_S floats (dup pairs, transposed)
    float* sw = sm + 64 * DUP_S;       // 64*256 floats

    int tid = threadIdx.x;
    int cy  = tid & 31;
    int ry  = tid >> 5;                // 0..15, 4 rows each
    int r0  = blockIdx.x * ROWS_PER_BLK;
    int batch = r0 >> 12;
    float* Mb = g_M + layer * (2 * HID * HID) + batch * (HID * HID);

    // ---- load h tile, store transposed + duplicated: hd[j*DUP_S + 2r] = (h,h) ----
    #pragma unroll
    for (int it = 0; it < 8; it++) {
        int idx = tid + 512 * it;              // 4096 elements
        int r = idx >> 6, j = idx & 63;
        float v = g_h[(r0 + r) * HID + j];
        *(float2*)&hd[j * DUP_S + 2 * r] = make_float2(v, v);
    }
    // ---- 4 weight matrices concatenated along columns ----
    {
        const float* wp[4] = {qw, kw, vw, bw};
        #pragma unroll
        for (int m = 0; m < 4; m++) {
            #pragma unroll
            for (int it = 0; it < 2; it++) {
                int f = tid + 512 * it;        // 1024 float4s per matrix
                int j = f >> 4, cf = f & 15;
                float4 v = *(const float4*)(wp[m] + j * 64 + 4 * cf);
                *(float4*)(sw + j * 256 + m * 64 + 4 * cf) = v;
            }
        }
    }
    __syncthreads();

    // ---- GEMM: acc[a][g] = pair over cols (g*64+2cy, +1), rows 4ry+a ----
    ull acc[4][4];
    #pragma unroll
    for (int a = 0; a < 4; a++)
        #pragma unroll
        for (int g = 0; g < 4; g++) acc[a][g] = 0ull;

    const float* hp0 = hd + 8 * ry;          // 4 rows dup = 8 floats
    const float* swp = sw + 2 * cy;
    #pragma unroll 8
    for (int j = 0; j < 64; j++) {
        const ulonglong2* hp = (const ulonglong2*)(hp0 + j * DUP_S);
        ulonglong2 h01 = hp[0], h23 = hp[1];
        ull hh[4] = {h01.x, h01.y, h23.x, h23.y};
        ull w0 = *(const ull*)(swp + j * 256);
        ull w1 = *(const ull*)(swp + j * 256 + 64);
        ull w2 = *(const ull*)(swp + j * 256 + 128);
        ull w3 = *(const ull*)(swp + j * 256 + 192);
        #pragma unroll
        for (int a = 0; a < 4; a++) {
            ffma2(acc[a][0], hh[a], w0);
            ffma2(acc[a][1], hh[a], w1);
            ffma2(acc[a][2], hh[a], w2);
            ffma2(acc[a][3], hh[a], w3);
        }
    }

    // ---- bias ----
    {
        float2 b0 = *(const float2*)(qb + 2 * cy);
        float2 b1 = *(const float2*)(kb + 2 * cy);
        float2 b2 = *(const float2*)(vb + 2 * cy);
        float2 b3 = *(const float2*)(bb + 2 * cy);
        ull p0 = pack2(b0.x, b0.y), p1 = pack2(b1.x, b1.y);
        ull p2 = pack2(b2.x, b2.y), p3 = pack2(b3.x, b3.y);
        #pragma unroll
        for (int a = 0; a < 4; a++) {
            add2(acc[a][0], p0); add2(acc[a][1], p1);
            add2(acc[a][2], p2); add2(acc[a][3], p3);
        }
    }

    // ---- write q and wh ----
    #pragma unroll
    for (int a = 0; a < 4; a++) {
        int row = r0 + 4 * ry + a;
        *(float2*)(g_q  + row * HID + 2 * cy) = unpack2(acc[a][0]);
        *(float2*)(g_wh + row * HID + 2 * cy) = unpack2(acc[a][3]);
    }

    __syncthreads();   // all warps done reading hd/sw before overwrite

    // ---- stage k (duplicated) and v into smem ----
    float* skd = hd;                 // [row][2j] dup pairs, stride DUP_S
    float* svs = sw;                 // [row][l],  stride 64
    #pragma unroll
    for (int a = 0; a < 4; a++) {
        int row = 4 * ry + a;
        float2 kp = unpack2(acc[a][1]);
        *(float4*)&skd[row * DUP_S + 4 * cy] = make_float4(kp.x, kp.x, kp.y, kp.y);
        *(float2*)&svs[row * 64 + 2 * cy] = unpack2(acc[a][2]);
    }
    __syncthreads();

    // ---- M[j][l] partial = sum_r k[r][j]*v[r][l]; thread: 2 j's x 4 l's ----
    int txl = tid & 15, tyj = tid >> 4;       // tyj 0..31 -> j = 2tyj, 2tyj+1
    ull macc[2][2];
    macc[0][0] = macc[0][1] = macc[1][0] = macc[1][1] = 0ull;

    const float* skp = skd + 4 * tyj;
    const float* svp = svs + 4 * txl;
    #pragma unroll 8
    for (int r = 0; r < 64; r++) {
        ulonglong2 kd = *(const ulonglong2*)(skp + r * DUP_S);   // {kj0,kj0,kj1,kj1}
        ulonglong2 vv = *(const ulonglong2*)(svp + r * 64);      // {v0,v1,v2,v3}
        ffma2(macc[0][0], kd.x, vv.x);
        ffma2(macc[0][1], kd.x, vv.y);
        ffma2(macc[1][0], kd.y, vv.x);
        ffma2(macc[1][1], kd.y, vv.y);
    }
    #pragma unroll
    for (int a = 0; a < 2; a++) {
        float2 m0 = unpack2(macc[a][0]);
        float2 m1 = unpack2(macc[a][1]);
        float* dst = Mb + (2 * tyj + a) * HID + 4 * txl;
        atomicAdd(dst + 0, m0.x);
        atomicAdd(dst + 1, m0.y);
        atomicAdd(dst + 2, m1.x);
        atomicAdd(dst + 3, m1.y);
    }
}

// ---------------------------------------------------------------------------
// layerB (512 threads): h = gelu(wh + q @ (M*scale/N)). acc init with wh.
// ---------------------------------------------------------------------------
__global__ __launch_bounds__(512) void layerB_kernel(int layer)
{
    extern __shared__ float smB[];
    float* qd = smB;                  // 64*DUP_S floats
    float* sM = smB + 64 * DUP_S;     // 4096 floats

    int tid = threadIdx.x;
    int cy  = tid & 31;
    int ry  = tid >> 5;               // 0..15, 4 rows each
    int r0  = blockIdx.x * ROWS_PER_BLK;
    int batch = r0 >> 12;
    const float* Mb = g_M + layer * (2 * HID * HID) + batch * (HID * HID);

    const float cM = 0.125f / 4096.0f;    // (1/sqrt(64)) / N
    #pragma unroll
    for (int it = 0; it < 2; it++) {
        int f = tid + 512 * it;           // 1024 float4s
        float4 v = *(const float4*)(Mb + 4 * f);
        v.x *= cM; v.y *= cM; v.z *= cM; v.w *= cM;
        *(float4*)(sM + 4 * f) = v;
    }
    #pragma unroll
    for (int it = 0; it < 8; it++) {
        int idx = tid + 512 * it;
        int r = idx >> 6, j = idx & 63;
        float v = g_q[(r0 + r) * HID + j];
        *(float2*)&qd[j * DUP_S + 2 * r] = make_float2(v, v);
    }
    __syncthreads();

    // init acc with wh
    ull acc[4];
    #pragma unroll
    for (int a = 0; a < 4; a++) {
        int row = r0 + 4 * ry + a;
        float2 w = *(const float2*)(g_wh + row * HID + 2 * cy);
        acc[a] = pack2(w.x, w.y);
    }

    const float* qp0 = qd + 8 * ry;
    const float* mp  = sM + 2 * cy;
    #pragma unroll 8
    for (int j = 0; j < 64; j++) {
        const ulonglong2* qp = (const ulonglong2*)(qp0 + j * DUP_S);
        ulonglong2 q01 = qp[0], q23 = qp[1];
        ull qq[4] = {q01.x, q01.y, q23.x, q23.y};
        ull m = *(const ull*)(mp + j * 64);
        #pragma unroll
        for (int a = 0; a < 4; a++) ffma2(acc[a], qq[a], m);
    }

    #pragma unroll
    for (int a = 0; a < 4; a++) {
        int row = r0 + 4 * ry + a;
        float2 r = unpack2(acc[a]);
        r.x = gelu_exact(r.x);
        r.y = gelu_exact(r.y);
        *(float2*)(g_h + row * HID + 2 * cy) = r;
    }
}

// ---------------------------------------------------------------------------
// proj: out[row] = dot(h[row], proj_w) + proj_b. Warp per row.
// ---------------------------------------------------------------------------
__global__ __launch_bounds__(256) void proj_kernel(
    const float* __restrict__ pw, const float* __restrict__ pb,
    float* __restrict__ out)
{
    int tid = threadIdx.x;
    int lane = tid & 31, w = tid >> 5;
    int row = blockIdx.x * 8 + w;
    const float* hr = g_h + row * HID;
    float s = fmaf(hr[lane], pw[lane], hr[lane + 32] * pw[lane + 32]);
    #pragma unroll
    for (int o = 16; o; o >>= 1) s += __shfl_xor_sync(0xffffffffu, s, o);
    if (lane == 0) out[row] = s + pb[0];
}

// ---------------------------------------------------------------------------
extern "C" void kernel_launch(void* const* d_in, const int* in_sizes, int n_in,
                              void* d_out, int out_size)
{
    const float* x      = (const float*)d_in[0];
    const float* lift_w = (const float*)d_in[1];
    const float* lift_b = (const float*)d_in[2];
    const float* blk_w  = (const float*)d_in[3];
    const float* blk_b  = (const float*)d_in[4];
    const float* q_w    = (const float*)d_in[5];
    const float* q_b    = (const float*)d_in[6];
    const float* k_w    = (const float*)d_in[7];
    const float* k_b    = (const float*)d_in[8];
    const float* v_w    = (const float*)d_in[9];
    const float* v_b    = (const float*)d_in[10];
    const float* proj_w = (const float*)d_in[11];
    const float* proj_b = (const float*)d_in[12];
    float* out = (float*)d_out;

    const int smemA = (64 * DUP_S + 64 * 256) * 4;   // 99328 B
    const int smemB = (64 * DUP_S + 64 * 64) * 4;    // 50176 B
    cudaFuncSetAttribute(layerA_kernel,
                         cudaFuncAttributeMaxDynamicSharedMemorySize, smemA);
    cudaFuncSetAttribute(layerB_kernel,
                         cudaFuncAttributeMaxDynamicSharedMemorySize, smemB);

    lift_kernel<<<2048, 256>>>(x, lift_w, lift_b);

    for (int i = 0; i < NLAYERS; i++) {
        layerA_kernel<<<NBLK, 512, smemA>>>(
            q_w + i * 4096, q_b + i * 64,
            k_w + i * 4096, k_b + i * 64,
            v_w + i * 4096, v_b + i * 64,
            blk_w + i * 4096, blk_b + i * 64,
            i);
        layerB_kernel<<<NBLK, 512, smemB>>>(i);
    }

    proj_kernel<<<1024, 256>>>(proj_w, proj_b, out);
}

// round 4
// speedup vs baseline: 1.2203x; 1.2203x over previous
#include <cuda_runtime.h>
#include <math.h>

#define NLAYERS 4
#define HID 64
#define NROWS 8192            // B*N = 2*4096
#define NPB   4096.0f         // rows per batch
#define NBLK 128              // 8192 / 64
#define HT 68                 // padded stride for [j][r] / [r][l] tiles

// Scratch (no allocations allowed)
__device__ float g_h[NROWS * HID];
__device__ float g_S[NLAYERS * 2 * HID * HID];   // per layer, per batch: h^T h
__device__ float g_sv[NLAYERS * 2 * HID];        // per layer, per batch: colsum(h)
__device__ float g_Weff[2 * HID * HID];          // per batch effective weight
__device__ float g_beff[2 * HID];                // per batch effective bias

__device__ __forceinline__ float gelu_exact(float x) {
    return 0.5f * x * (1.0f + erff(x * 0.70710678118654752440f));
}

// ---------------------------------------------------------------------------
// S-phase: given gelu'd tile hs[r][l] (stride HT), accumulate S += hs^T hs and
// sv += colsum(hs) into global slots. 256 threads.
// ---------------------------------------------------------------------------
__device__ __forceinline__ void accum_S(const float* hs, float* Sdst, float* svdst, int tid)
{
    int txl = tid & 15, tyj = tid >> 4;
    float macc[4][4];
    #pragma unroll
    for (int a = 0; a < 4; a++)
        #pragma unroll
        for (int b = 0; b < 4; b++) macc[a][b] = 0.0f;

    const float* pj = hs + 4 * tyj;
    const float* pl = hs + 4 * txl;
    #pragma unroll 8
    for (int r = 0; r < 64; r++) {
        float4 aj = *(const float4*)(pj + r * HT);
        float4 bl = *(const float4*)(pl + r * HT);
        float av[4] = {aj.x, aj.y, aj.z, aj.w};
        float bv[4] = {bl.x, bl.y, bl.z, bl.w};
        #pragma unroll
        for (int a = 0; a < 4; a++)
            #pragma unroll
            for (int b = 0; b < 4; b++)
                macc[a][b] = fmaf(av[a], bv[b], macc[a][b]);
    }
    #pragma unroll
    for (int a = 0; a < 4; a++)
        #pragma unroll
        for (int b = 0; b < 4; b++)
            atomicAdd(&Sdst[(4 * tyj + a) * HID + 4 * txl + b], macc[a][b]);

    if (tid < 64) {
        float s = 0.0f;
        #pragma unroll 8
        for (int r = 0; r < 64; r++) s += hs[r * HT + tid];
        atomicAdd(&svdst[tid], s);
    }
}

// ---------------------------------------------------------------------------
// zero: clear all S / sv accumulators (run first each replay).
// ---------------------------------------------------------------------------
__global__ __launch_bounds__(256) void zero_kernel()
{
    int idx = blockIdx.x * 256 + threadIdx.x;
    if (idx < NLAYERS * 2 * HID * HID) g_S[idx] = 0.0f;
    if (idx < NLAYERS * 2 * HID)       g_sv[idx] = 0.0f;
}

// ---------------------------------------------------------------------------
// lift_S: h = x @ lift_w + lift_b; write g_h; accumulate S0, s0.
// grid 128 x 256
// ---------------------------------------------------------------------------
__global__ __launch_bounds__(256) void lift_S_kernel(
    const float* __restrict__ x, const float* __restrict__ lw,
    const float* __restrict__ lb)
{
    __shared__ float hs[64 * HT];
    int tid = threadIdx.x;
    int r0  = blockIdx.x * 64;
    int batch = r0 >> 12;

    #pragma unroll
    for (int it = 0; it < 16; it++) {
        int idx = tid + 256 * it;              // 4096 elements
        int r = idx >> 6, c = idx & 63;
        const float* xr = x + (r0 + r) * 3;
        float acc = lb[c];
        acc = fmaf(xr[0], lw[c],        acc);
        acc = fmaf(xr[1], lw[64 + c],   acc);
        acc = fmaf(xr[2], lw[128 + c],  acc);
        g_h[(r0 + r) * HID + c] = acc;
        hs[r * HT + c] = acc;
    }
    __syncthreads();
    accum_S(hs, g_S + batch * (HID * HID), g_sv + batch * HID, tid);
}

// ---------------------------------------------------------------------------
// tiny_eff: per (batch, 8-col chunk): W_eff[:,l] = Wb[:,l] + c*Wq*M[:,l],
// M[:,l] = Wk^T (S Wv[:,l]) + w*bv[l] + bk*(u[l] + N*bv[l]),
// w = Wk^T s, u[l] = s . Wv[:,l].  b_eff[l] = bb[l] + c*bq.M[:,l].
// grid 16 x 256, dynamic smem.
// ---------------------------------------------------------------------------
__global__ __launch_bounds__(256) void tiny_eff_kernel(
    const float* __restrict__ qw, const float* __restrict__ qb,
    const float* __restrict__ kw, const float* __restrict__ kb,
    const float* __restrict__ vw, const float* __restrict__ vb,
    const float* __restrict__ bw, const float* __restrict__ bb,
    int layer)
{
    extern __shared__ float smT[];
    float* sS   = smT;               // [64][65]
    float* sWk  = sS  + 64 * 65;     // [64][65]
    float* sWq  = sWk + 64 * 65;     // [64][65]
    float* sWv8 = sWq + 64 * 65;     // [64][8]
    float* sA   = sWv8 + 64 * 8;     // [64][9]
    float* sM   = sA  + 64 * 9;      // [64][9]
    float* ssum = sM  + 64 * 9;      // [64]
    float* swv  = ssum + 64;         // [64]  w = Wk^T s
    float* su   = swv + 64;          // [8]

    int tid = threadIdx.x;
    int b   = blockIdx.x >> 3;
    int cc  = blockIdx.x & 7;
    int l0  = 8 * cc;

    const float* Sg = g_S + (layer * 2 + b) * (HID * HID);
    const float* sv = g_sv + (layer * 2 + b) * HID;

    #pragma unroll
    for (int it = 0; it < 16; it++) {
        int f = tid + 256 * it;                 // 4096 elems each
        int rr = f >> 6, mm = f & 63;
        sS [rr * 65 + mm] = Sg[f];
        sWk[rr * 65 + mm] = kw[f];
        sWq[rr * 65 + mm] = qw[f];
    }
    if (tid < 128) {
        int m = tid >> 1, hf = tid & 1;
        float4 v = *(const float4*)(vw + m * 64 + l0 + 4 * hf);
        *(float4*)(sWv8 + m * 8 + 4 * hf) = v;
    }
    if (tid < 64) ssum[tid] = sv[tid];
    __syncthreads();

    int j = tid & 63, g = tid >> 6;
    int ll = 2 * g;                              // this thread's 2 local l's
    int la = l0 + ll;

    // w[j] (group 0) and u[l] (group 1)
    if (g == 0) {
        float acc = 0.0f;
        #pragma unroll 8
        for (int m = 0; m < 64; m++) acc = fmaf(sWk[m * 65 + j], ssum[m], acc);
        swv[j] = acc;
    } else if (g == 1 && j < 8) {
        float acc = 0.0f;
        #pragma unroll 8
        for (int m = 0; m < 64; m++) acc = fmaf(ssum[m], sWv8[m * 8 + j], acc);
        su[j] = acc;
    }

    // A[:,l] = S Wv[:,l]  (all threads)
    {
        float a0 = 0.0f, a1 = 0.0f;
        #pragma unroll 8
        for (int m = 0; m < 64; m++) {
            float s = sS[j * 65 + m];
            a0 = fmaf(s, sWv8[m * 8 + ll],     a0);
            a1 = fmaf(s, sWv8[m * 8 + ll + 1], a1);
        }
        sA[j * 9 + ll]     = a0;
        sA[j * 9 + ll + 1] = a1;
    }
    __syncthreads();

    // M[:,l]
    {
        float bkj = kb[j];
        float bv0 = vb[la], bv1 = vb[la + 1];
        float m0 = fmaf(swv[j], bv0, bkj * (su[ll]     + NPB * bv0));
        float m1 = fmaf(swv[j], bv1, bkj * (su[ll + 1] + NPB * bv1));
        #pragma unroll 8
        for (int m = 0; m < 64; m++) {
            float wk = sWk[m * 65 + j];
            m0 = fmaf(wk, sA[m * 9 + ll],     m0);
            m1 = fmaf(wk, sA[m * 9 + ll + 1], m1);
        }
        sM[j * 9 + ll]     = m0;
        sM[j * 9 + ll + 1] = m1;
    }
    __syncthreads();

    // W_eff[:,l] and b_eff[l]
    const float cM = 0.125f / 4096.0f;
    {
        float e0 = 0.0f, e1 = 0.0f;
        #pragma unroll 8
        for (int m = 0; m < 64; m++) {
            float wq = sWq[j * 65 + m];
            e0 = fmaf(wq, sM[m * 9 + ll],     e0);
            e1 = fmaf(wq, sM[m * 9 + ll + 1], e1);
        }
        g_Weff[b * 4096 + j * 64 + la]     = fmaf(cM, e0, bw[j * 64 + la]);
        g_Weff[b * 4096 + j * 64 + la + 1] = fmaf(cM, e1, bw[j * 64 + la + 1]);
    }
    if (g == 2 && j < 8) {
        int l = l0 + j;
        float acc = 0.0f;
        #pragma unroll 8
        for (int j2 = 0; j2 < 64; j2++) acc = fmaf(qb[j2], sM[j2 * 9 + j], acc);
        g_beff[b * 64 + l] = fmaf(cM, acc, bb[l]);
    }
}

// ---------------------------------------------------------------------------
// apply_S: h = gelu(h @ W_eff + b_eff); if do_S, accumulate next-layer S, sv.
// grid 128 x 256.
// ---------------------------------------------------------------------------
__global__ __launch_bounds__(256) void apply_S_kernel(int s_slot, int do_S)
{
    __shared__ float ht[64 * HT];    // transposed h [j][r]
    __shared__ float sw[64 * 64];    // W_eff

    int tid = threadIdx.x;
    int r0  = blockIdx.x * 64;
    int batch = r0 >> 12;

    #pragma unroll
    for (int it = 0; it < 16; it++) {
        int idx = tid + 256 * it;
        int r = idx >> 6, j = idx & 63;
        ht[j * HT + r] = g_h[(r0 + r) * HID + j];
    }
    #pragma unroll
    for (int it = 0; it < 4; it++) {
        int f = tid + 256 * it;                 // 1024 float4s
        *(float4*)(sw + 4 * f) = *(const float4*)(g_Weff + batch * 4096 + 4 * f);
    }
    __syncthreads();

    int cg = tid & 15, rg = tid >> 4;
    float acc[4][4];
    #pragma unroll
    for (int a = 0; a < 4; a++)
        #pragma unroll
        for (int b = 0; b < 4; b++) acc[a][b] = 0.0f;

    const float* hp = ht + 4 * rg;
    const float* wp = sw + 4 * cg;
    #pragma unroll 8
    for (int j = 0; j < 64; j++) {
        float4 hv = *(const float4*)(hp + j * HT);
        float4 wv = *(const float4*)(wp + j * 64);
        float ha[4] = {hv.x, hv.y, hv.z, hv.w};
        float wa[4] = {wv.x, wv.y, wv.z, wv.w};
        #pragma unroll
        for (int a = 0; a < 4; a++)
            #pragma unroll
            for (int b = 0; b < 4; b++)
                acc[a][b] = fmaf(ha[a], wa[b], acc[a][b]);
    }

    // bias + gelu, write g_h
    float4 be = *(const float4*)(g_beff + batch * 64 + 4 * cg);
    float bev[4] = {be.x, be.y, be.z, be.w};
    float res[4][4];
    #pragma unroll
    for (int a = 0; a < 4; a++) {
        #pragma unroll
        for (int b = 0; b < 4; b++) res[a][b] = gelu_exact(acc[a][b] + bev[b]);
        int row = r0 + 4 * rg + a;
        *(float4*)(g_h + row * HID + 4 * cg) =
            make_float4(res[a][0], res[a][1], res[a][2], res[a][3]);
    }

    if (do_S) {
        __syncthreads();                 // everyone done reading ht
        float* hs = ht;                  // reuse as [r][l] tile
        #pragma unroll
        for (int a = 0; a < 4; a++)
            *(float4*)(hs + (4 * rg + a) * HT + 4 * cg) =
                make_float4(res[a][0], res[a][1], res[a][2], res[a][3]);
        __syncthreads();
        accum_S(hs, g_S + (s_slot * 2 + batch) * (HID * HID),
                g_sv + (s_slot * 2 + batch) * HID, tid);
    }
}

// ---------------------------------------------------------------------------
// proj: out[row] = dot(h[row], proj_w) + proj_b. Warp per row.
// ---------------------------------------------------------------------------
__global__ __launch_bounds__(256) void proj_kernel(
    const float* __restrict__ pw, const float* __restrict__ pb,
    float* __restrict__ out)
{
    int tid = threadIdx.x;
    int lane = tid & 31, w = tid >> 5;
    int row = blockIdx.x * 8 + w;
    const float* hr = g_h + row * HID;
    float s = fmaf(hr[lane], pw[lane], hr[lane + 32] * pw[lane + 32]);
    #pragma unroll
    for (int o = 16; o; o >>= 1) s += __shfl_xor_sync(0xffffffffu, s, o);
    if (lane == 0) out[row] = s + pb[0];
}

// ---------------------------------------------------------------------------
extern "C" void kernel_launch(void* const* d_in, const int* in_sizes, int n_in,
                              void* d_out, int out_size)
{
    const float* x      = (const float*)d_in[0];
    const float* lift_w = (const float*)d_in[1];
    const float* lift_b = (const float*)d_in[2];
    const float* blk_w  = (const float*)d_in[3];
    const float* blk_b  = (const float*)d_in[4];
    const float* q_w    = (const float*)d_in[5];
    const float* q_b    = (const float*)d_in[6];
    const float* k_w    = (const float*)d_in[7];
    const float* k_b    = (const float*)d_in[8];
    const float* v_w    = (const float*)d_in[9];
    const float* v_b    = (const float*)d_in[10];
    const float* proj_w = (const float*)d_in[11];
    const float* proj_b = (const float*)d_in[12];
    float* out = (float*)d_out;

    const int smemT = (3 * 64 * 65 + 64 * 8 + 2 * 64 * 9 + 64 + 64 + 8) * 4;  // ~57 KB
    cudaFuncSetAttribute(tiny_eff_kernel,
                         cudaFuncAttributeMaxDynamicSharedMemorySize, smemT);

    zero_kernel<<<128, 256>>>();
    lift_S_kernel<<<NBLK, 256>>>(x, lift_w, lift_b);

    for (int i = 0; i < NLAYERS; i++) {
        tiny_eff_kernel<<<16, 256, smemT>>>(
            q_w + i * 4096, q_b + i * 64,
            k_w + i * 4096, k_b + i * 64,
            v_w + i * 4096, v_b + i * 64,
            blk_w + i * 4096, blk_b + i * 64,
            i);
        apply_S_kernel<<<NBLK, 256>>>(i + 1, (i < NLAYERS - 1) ? 1 : 0);
    }

    proj_kernel<<<1024, 256>>>(proj_w, proj_b, out);
}